// round 16
// baseline (speedup 1.0000x reference)
#include <cuda_runtime.h>
#include <cuda_fp16.h>
#include <cstdint>

#define BS 4
#define NS 1024
#define D 2048
#define H 16
#define DHD 128
#define SCALE 0.08838834764831845f
#define MASK_BIAS -1e9f
#define LOG2E 1.4426950408889634f
#define SCALE_L2E 0.12753139526763867f   /* SCALE * log2(e) */
#define M_ROWS (BS * NS)   /* 4096 */
#define N_QKV (3 * D)      /* 6144 */

// ---------------- scratch (static device globals; no allocation) ----------
__device__ __half g_x0[M_ROWS * D];
__device__ __half g_wi0[N_QKV * D];
__device__ __half g_wo0[D * D];
__device__ __half g_o0[M_ROWS * D];
// q,k: hi only, [b,h,seq,dh]; v: hi only, TRANSPOSED [b,h,dh,seq]
__device__ __half g_q0[BS*H*NS*DHD];
__device__ __half g_k0[BS*H*NS*DHD];
__device__ __half g_v0[BS*H*NS*DHD];

// ---------------- helpers ---------------------------------------------------
__device__ __forceinline__ uint32_t smem_to_u32(const void* p) {
    uint32_t a;
    asm("{ .reg .u64 t; cvta.to.shared.u64 t, %1; cvt.u32.u64 %0, t; }"
        : "=r"(a) : "l"(p));
    return a;
}
#define CP_ASYNC16(dst, src) \
    asm volatile("cp.async.cg.shared.global [%0], [%1], 16;" \
                 :: "r"((uint32_t)(dst)), "l"(src) : "memory")
#define CP_COMMIT() asm volatile("cp.async.commit_group;" ::: "memory")
#define CP_WAIT(n)  asm volatile("cp.async.wait_group %0;" :: "n"(n) : "memory")

__device__ __forceinline__ void ldsm4(uint32_t r[4], uint32_t addr) {
    asm volatile("ldmatrix.sync.aligned.m8n8.x4.shared.b16 {%0,%1,%2,%3}, [%4];"
                 : "=r"(r[0]), "=r"(r[1]), "=r"(r[2]), "=r"(r[3]) : "r"(addr));
}
__device__ __forceinline__ void mma_f32(float c[4], const uint32_t a[4],
                                        const uint32_t b0, const uint32_t b1) {
    asm volatile(
        "mma.sync.aligned.m16n8k16.row.col.f32.f16.f16.f32 "
        "{%0,%1,%2,%3}, {%4,%5,%6,%7}, {%8,%9}, {%0,%1,%2,%3};"
        : "+f"(c[0]), "+f"(c[1]), "+f"(c[2]), "+f"(c[3])
        : "r"(a[0]), "r"(a[1]), "r"(a[2]), "r"(a[3]), "r"(b0), "r"(b1));
}
__device__ __forceinline__ uint32_t packh(__half a, __half b) {
    __half2 t = __halves2half2(a, b);
    return *reinterpret_cast<uint32_t*>(&t);
}
__device__ __forceinline__ float ex2f(float x) {
    float r;
    asm("ex2.approx.f32 %0, %1;" : "=f"(r) : "f"(x));
    return r;
}
__device__ __forceinline__ uint32_t swz128(int row, int ch) {
    return (uint32_t)(row * 128 + ((ch ^ (row & 7)) << 4));
}
__device__ __forceinline__ uint32_t swz256(int row, int ch) {
    return (uint32_t)(row * 256 + ((ch ^ ((row & 7) << 1)) << 4));
}

// ---------------- fused split: fp32 -> fp16 hi only -----------------------
#define NX4  (M_ROWS * D / 4)
#define NWI4 (N_QKV * D / 4)
#define NWO4 (D * D / 4)
__global__ void __launch_bounds__(256) split_all(const float4* __restrict__ x,
                                                 const float4* __restrict__ wi,
                                                 const float4* __restrict__ wo)
{
    int i = blockIdx.x * 256 + threadIdx.x;
    const float4* src;
    __half* o0;
    int j;
    if (i < NX4)                    { src = x;  o0 = g_x0;  j = i; }
    else if (i < NX4 + NWI4)        { src = wi; o0 = g_wi0; j = i - NX4; }
    else if (i < NX4 + NWI4 + NWO4) { src = wo; o0 = g_wo0; j = i - NX4 - NWI4; }
    else return;
    float4 v = src[j];
    *(uint32_t*)&o0[4 * j]     = packh(__float2half_rn(v.x), __float2half_rn(v.y));
    *(uint32_t*)&o0[4 * j + 2] = packh(__float2half_rn(v.z), __float2half_rn(v.w));
}

// ---------------- mma.sync fp16 GEMM: C[M,N] = A0 @ B0^T ------------------
// 128x128 tile, K-slab 64, 8 warps, 1 pass, 32KB stage, 3-stage, 2 CTAs/SM.
#define KSLAB 64
#define NCH (D / KSLAB)        /* 32 */
#define TILE_BYTES (128 * 128)
#define ST_B TILE_BYTES
#define STAGE (2 * TILE_BYTES)             /* 32 KB */
#define GEMM_DYN (3 * STAGE + 1024)
#define TRS 136                            /* transpose buffer stride (halfs) */

template<int EPI>
__global__ void __launch_bounds__(256, 2) gemm_mma(const float* __restrict__ bias,
                                                   float* __restrict__ Cout)
{
    extern __shared__ char dsm[];
    const uint32_t base = (smem_to_u32(dsm) + 1023u) & ~1023u;
    const int tid = threadIdx.x, lane = tid & 31, wid = tid >> 5;
    const int wm = wid >> 1, wn = wid & 1;
    const int row0 = blockIdx.y * 128, col0 = blockIdx.x * 128;

    const __half* A0 = EPI == 0 ? g_x0  : g_o0;
    const __half* B0 = EPI == 0 ? g_wi0 : g_wo0;

    float acc[2][8][4] = {};

    auto load_stage = [&](int c, int s) {
        const uint32_t sb = base + s * STAGE;
        const int k0 = c * KSLAB;
        const int ch = tid & 7;
        const int rb = tid >> 3;
#pragma unroll
        for (int i = 0; i < 8; i++) {
            const int tile = i >> 2;
            const int r = rb + 32 * (i & 3);
            const __half* src = (tile == 0)
                ? A0 + (size_t)(row0 + r) * D + k0 + ch * 8
                : B0 + (size_t)(col0 + r) * D + k0 + ch * 8;
            CP_ASYNC16(sb + tile * ST_B + swz128(r, ch), src);
        }
    };

    load_stage(0, 0); CP_COMMIT();
    load_stage(1, 1); CP_COMMIT();

    const int a_rowl = (lane & 7) + ((lane >> 3) & 1) * 8;
    const int a_chh  = lane >> 4;
    const int b_rowl = (lane & 7) + (lane >> 4) * 8;
    const int b_chh  = (lane >> 3) & 1;

    uint32_t a0f[2][2][4], b0f[2][4][4];

    for (int c = 0; c < NCH; c++) {
        if (c + 2 < NCH) { CP_WAIT(1); } else { CP_WAIT(0); }
        __syncthreads();
        if (c + 2 < NCH) { load_stage(c + 2, (c + 2) % 3); CP_COMMIT(); }

        const uint32_t sb = base + (c % 3) * STAGE;

        auto load_frags = [&](int kk, int buf) {
#pragma unroll
            for (int mt = 0; mt < 2; mt++) {
                int row = wm * 32 + mt * 16 + a_rowl;
                ldsm4(a0f[buf][mt], sb + swz128(row, 2 * kk + a_chh));
            }
#pragma unroll
            for (int ng = 0; ng < 4; ng++) {
                int row = wn * 64 + ng * 16 + b_rowl;
                ldsm4(b0f[buf][ng], sb + ST_B + swz128(row, 2 * kk + b_chh));
            }
        };

        load_frags(0, 0);
#pragma unroll
        for (int kk = 0; kk < 4; kk++) {
            if (kk < 3) load_frags(kk + 1, (kk + 1) & 1);
            const int bf = kk & 1;
#pragma unroll
            for (int mt = 0; mt < 2; mt++)
#pragma unroll
                for (int ng = 0; ng < 4; ng++) {
                    mma_f32(acc[mt][2 * ng],     a0f[bf][mt], b0f[bf][ng][0], b0f[bf][ng][1]);
                    mma_f32(acc[mt][2 * ng + 1], a0f[bf][mt], b0f[bf][ng][2], b0f[bf][ng][3]);
                }
        }
    }

    // epilogue
    const int g = lane >> 2, tig = lane & 3;
    if (EPI == 0 && col0 >= 2 * D) {
        // v columns: transpose through smem, coalesced writes to [b,h,dh,seq]
        __half* trbuf = (__half*)dsm;
        __syncthreads();                  // all warps done with pipeline smem
#pragma unroll
        for (int mt = 0; mt < 2; mt++)
#pragma unroll
            for (int nt = 0; nt < 8; nt++) {
                int cc = wn * 64 + nt * 8 + 2 * tig;      // local d 0..127
                int ml = wm * 32 + mt * 16 + g;           // local seq 0..127
                trbuf[cc * TRS + ml]           = __float2half_rn(acc[mt][nt][0]);
                trbuf[(cc + 1) * TRS + ml]     = __float2half_rn(acc[mt][nt][1]);
                trbuf[cc * TRS + ml + 8]       = __float2half_rn(acc[mt][nt][2]);
                trbuf[(cc + 1) * TRS + ml + 8] = __float2half_rn(acc[mt][nt][3]);
            }
        __syncthreads();
        const int hh = (col0 >> 7) & 15;
        const int bb = row0 >> 10;
        const int sr0 = row0 & 1023;
        __half* vbase = g_v0 + ((size_t)(bb * H + hh)) * DHD * NS + sr0;
#pragma unroll
        for (int i = 0; i < 8; i++) {
            int idx = tid + 256 * i;
            int r = idx >> 4;              // d row 0..127
            int cw = idx & 15;             // 16B chunk along seq
            *(float4*)&vbase[(size_t)r * NS + cw * 8] =
                *(float4*)&trbuf[r * TRS + cw * 8];
        }
        return;
    }
#pragma unroll
    for (int mt = 0; mt < 2; mt++) {
#pragma unroll
        for (int nt = 0; nt < 8; nt++) {
            int colg = col0 + wn * 64 + nt * 8 + 2 * tig;
            int mA = row0 + wm * 32 + mt * 16 + g;
            int mB = mA + 8;
            float2 vA = make_float2(acc[mt][nt][0], acc[mt][nt][1]);
            float2 vB = make_float2(acc[mt][nt][2], acc[mt][nt][3]);
            if (EPI == 0) {
                int which = colg >> 11, hh = (colg >> 7) & 15, d0 = colg & 127;
                int bbA = mA >> 10, srA = mA & 1023;
                int bbB = mB >> 10, srB = mB & 1023;
                __half* p0 = which ? g_k0 : g_q0;
                size_t iA = ((size_t)(bbA * H + hh) * NS + srA) * DHD + d0;
                size_t iB = ((size_t)(bbB * H + hh) * NS + srB) * DHD + d0;
                *(uint32_t*)&p0[iA] = packh(__float2half_rn(vA.x), __float2half_rn(vA.y));
                *(uint32_t*)&p0[iB] = packh(__float2half_rn(vB.x), __float2half_rn(vB.y));
            } else {
                float b0v = bias[colg], b1v = bias[colg + 1];
                vA.x += b0v; vA.y += b1v;
                vB.x += b0v; vB.y += b1v;
                *(float2*)&Cout[(size_t)mA * D + colg] = vA;
                *(float2*)&Cout[(size_t)mB * D + colg] = vB;
            }
        }
    }
}

// ---------------- attention: flash, static-max softmax, direct ex2 --------
#define AQ0_OFF 0
#define AK_OFF(s) (32768 + (s) * 32768)
#define AV_OFF(s) (32768 + (s) * 32768 + 16384)
#define ATTN_DYN (32768 + 2 * 32768 + 1024)

__global__ void __launch_bounds__(256, 2) attn_mma(const int* __restrict__ ids)
{
    extern __shared__ char dsm[];
    __shared__ float bks[NS];
    const uint32_t base = (smem_to_u32(dsm) + 1023u) & ~1023u;
    const int tid = threadIdx.x, lane = tid & 31, wid = tid >> 5;
    const int g = lane >> 2, tig = lane & 3;
    const int qt = blockIdx.x, h = blockIdx.y, b = blockIdx.z;
    const int bh = b * H + h;
    const size_t qk_base = (size_t)bh * NS * DHD;

    // precompute log2-scaled mask bias for the whole key row
    {
        const int ids_base = b * NS;
        const float mbs = MASK_BIAS * SCALE_L2E;
#pragma unroll
        for (int i = 0; i < NS / 256; i++)
            bks[tid + 256 * i] = mbs * (float)__ldg(&ids[ids_base + tid + 256 * i]);
    }

    auto load_q = [&]() {
        const int qrow0 = qt * 128;
#pragma unroll
        for (int i = 0; i < 8; i++) {
            int idx = tid + 256 * i;
            int r = (idx >> 4) & 127;
            int ch = idx & 15;
            const __half* src = g_q0 + qk_base + (size_t)(qrow0 + r) * DHD + ch * 8;
            CP_ASYNC16(base + AQ0_OFF + swz256(r, ch), src);
        }
    };
    auto load_kv = [&](int kt, int s) {
#pragma unroll
        for (int i = 0; i < 4; i++) {
            int idx = tid + 256 * i;
            int r = idx >> 4;
            int ch = idx & 15;
            const __half* src = g_k0 +
                qk_base + (size_t)(kt * 64 + r) * DHD + ch * 8;
            CP_ASYNC16(base + AK_OFF(s) + swz256(r, ch), src);
        }
#pragma unroll
        for (int i = 0; i < 4; i++) {
            int idx = tid + 256 * i;
            int r = idx >> 3;
            int ch = idx & 7;
            const __half* src = g_v0 +
                (size_t)bh * DHD * NS + (size_t)r * NS + kt * 64 + ch * 8;
            CP_ASYNC16(base + AV_OFF(s) + swz128(r, ch), src);
        }
    };

    load_q(); load_kv(0, 0); CP_COMMIT();
    load_kv(1, 1); CP_COMMIT();

    const int a_row = wid * 16 + (lane & 7) + ((lane >> 3) & 1) * 8;
    const int a_chh = lane >> 4;
    const int b_rowl = (lane & 7) + (lane >> 4) * 8;
    const int b_chh = (lane >> 3) & 1;

    float l0 = 0.f, l1 = 0.f;
    float o[16][4] = {};

    for (int kt = 0; kt < 16; kt++) {
        if (kt + 1 < 16) { CP_WAIT(1); } else { CP_WAIT(0); }
        __syncthreads();

        const uint32_t sbK = base + AK_OFF(kt & 1);
        const uint32_t sbV = base + AV_OFF(kt & 1);

        // ---- S = Q0 @ K0^T ----
        float s[8][4] = {};
#pragma unroll
        for (int kk = 0; kk < 8; kk++) {
            uint32_t aq0[4];
            ldsm4(aq0, base + AQ0_OFF + swz256(a_row, 2 * kk + a_chh));
#pragma unroll
            for (int ng = 0; ng < 4; ng++) {
                uint32_t k0f[4];
                ldsm4(k0f, sbK + swz256(ng * 16 + b_rowl, 2 * kk + b_chh));
                mma_f32(s[2 * ng],     aq0, k0f[0], k0f[1]);
                mma_f32(s[2 * ng + 1], aq0, k0f[2], k0f[3]);
            }
        }

        // ---- p = exp2(s*SCALE_L2E + bias2), static max 0; accumulate l ----
#pragma unroll
        for (int j = 0; j < 8; j++) {
            int c = kt * 64 + 8 * j + 2 * tig;
            float bc0 = bks[c];
            float bc1 = bks[c + 1];
            s[j][0] = ex2f(fmaf(s[j][0], SCALE_L2E, bc0));
            s[j][1] = ex2f(fmaf(s[j][1], SCALE_L2E, bc1));
            s[j][2] = ex2f(fmaf(s[j][2], SCALE_L2E, bc0));
            s[j][3] = ex2f(fmaf(s[j][3], SCALE_L2E, bc1));
            l0 += s[j][0] + s[j][1];
            l1 += s[j][2] + s[j][3];
        }

        // ---- O += P0 @ V0 ----
#pragma unroll
        for (int kc = 0; kc < 4; kc++) {
            uint32_t ap0[4];
            ap0[0] = packh(__float2half_rn(s[2*kc][0]),   __float2half_rn(s[2*kc][1]));
            ap0[1] = packh(__float2half_rn(s[2*kc][2]),   __float2half_rn(s[2*kc][3]));
            ap0[2] = packh(__float2half_rn(s[2*kc+1][0]), __float2half_rn(s[2*kc+1][1]));
            ap0[3] = packh(__float2half_rn(s[2*kc+1][2]), __float2half_rn(s[2*kc+1][3]));
#pragma unroll
            for (int nv = 0; nv < 8; nv++) {
                uint32_t v0f[4];
                ldsm4(v0f, sbV + swz128(nv * 16 + b_rowl, 2 * kc + b_chh));
                mma_f32(o[2 * nv],     ap0, v0f[0], v0f[1]);
                mma_f32(o[2 * nv + 1], ap0, v0f[2], v0f[3]);
            }
        }
        __syncthreads();
        if (kt + 2 < 16) { load_kv(kt + 2, kt & 1); CP_COMMIT(); }
    }

    // ---- single l reduction across the quad ----
    l0 += __shfl_xor_sync(0xFFFFFFFF, l0, 1);
    l0 += __shfl_xor_sync(0xFFFFFFFF, l0, 2);
    l1 += __shfl_xor_sync(0xFFFFFFFF, l1, 1);
    l1 += __shfl_xor_sync(0xFFFFFFFF, l1, 2);

    // ---- normalize + write o (fp16 hi only) [b, seq, D] ----
    float il0 = 1.0f / l0, il1 = 1.0f / l1;
    const int r0 = qt * 128 + wid * 16 + g;
    const int r1 = r0 + 8;
#pragma unroll
    for (int nt = 0; nt < 16; nt++) {
        int dcol = h * DHD + nt * 8 + 2 * tig;
        size_t i0 = (size_t)(b * NS + r0) * D + dcol;
        size_t i1 = (size_t)(b * NS + r1) * D + dcol;
        *(uint32_t*)&g_o0[i0] = packh(__float2half_rn(o[nt][0] * il0),
                                      __float2half_rn(o[nt][1] * il0));
        *(uint32_t*)&g_o0[i1] = packh(__float2half_rn(o[nt][2] * il1),
                                      __float2half_rn(o[nt][3] * il1));
    }
}

// ---------------- launch ---------------------------------------------------
extern "C" void kernel_launch(void* const* d_in, const int* in_sizes, int n_in,
                              void* d_out, int out_size)
{
    const float* x     = (const float*)d_in[0];
    const int*   ids   = (const int*)d_in[1];
    const float* w_in  = (const float*)d_in[2];
    const float* w_out = (const float*)d_in[3];
    const float* b_out = (const float*)d_in[4];
    float* out = (float*)d_out;

    cudaFuncSetAttribute(gemm_mma<0>,
                         cudaFuncAttributeMaxDynamicSharedMemorySize, GEMM_DYN);
    cudaFuncSetAttribute(gemm_mma<1>,
                         cudaFuncAttributeMaxDynamicSharedMemorySize, GEMM_DYN);
    cudaFuncSetAttribute(attn_mma,
                         cudaFuncAttributeMaxDynamicSharedMemorySize, ATTN_DYN);

    const int total4 = NX4 + NWI4 + NWO4;
    split_all<<<(total4 + 255) / 256, 256>>>((const float4*)x, (const float4*)w_in,
                                             (const float4*)w_out);

    gemm_mma<0><<<dim3(N_QKV / 128, M_ROWS / 128), 256, GEMM_DYN>>>(nullptr, nullptr);
    attn_mma<<<dim3(NS / 128, H, BS), 256, ATTN_DYN>>>(ids);
    gemm_mma<1><<<dim3(D / 128, M_ROWS / 128), 256, GEMM_DYN>>>(b_out, out);
}